// round 6
// baseline (speedup 1.0000x reference)
#include <cuda_runtime.h>
#include <cstdint>

// ---------------------------------------------------------------------------
// StructureEmbeddingLayer
//   B=128, N=48, E=64, D=256, M=N+1=49
//   out[b,i,j,:] = virtual_edge_emb                      (i==0 || j==0)
//                = LN(sum of 4 table_sc rows) + LN(x8 @ W_sf + b_sf)   (else)
//   plus scatter-add of per-bond hb into (i0,i1) and hb@W_rev+b_rev into (i1,i0)
// ---------------------------------------------------------------------------

typedef unsigned long long U64;

// ---- packed f32x2 helpers (sm_100+) ----
__device__ __forceinline__ U64 f2pk(float lo, float hi) {
    U64 r;
    asm("mov.b64 %0, {%1, %2};" : "=l"(r)
        : "r"(__float_as_uint(lo)), "r"(__float_as_uint(hi)));
    return r;
}
__device__ __forceinline__ void f2un(U64 v, float& lo, float& hi) {
    unsigned a, b;
    asm("mov.b64 {%0, %1}, %2;" : "=r"(a), "=r"(b) : "l"(v));
    lo = __uint_as_float(a); hi = __uint_as_float(b);
}
__device__ __forceinline__ U64 f2dup(float x) { return f2pk(x, x); }
__device__ __forceinline__ U64 f2add(U64 a, U64 b) {
    U64 r; asm("add.rn.f32x2 %0, %1, %2;" : "=l"(r) : "l"(a), "l"(b)); return r;
}
__device__ __forceinline__ U64 f2mul(U64 a, U64 b) {
    U64 r; asm("mul.rn.f32x2 %0, %1, %2;" : "=l"(r) : "l"(a), "l"(b)); return r;
}
__device__ __forceinline__ U64 f2fma(U64 a, U64 b, U64 c) {
    U64 r; asm("fma.rn.f32x2 %0, %1, %2, %3;" : "=l"(r) : "l"(a), "l"(b), "l"(c)); return r;
}

// ---- scratch (no cudaMalloc allowed) ----
__device__ float g_hb [8192 * 256];   // masked bond embedding  [B*E, D]
__device__ float g_rev[8192 * 256];   // hb @ W_rev + b_rev     [B*E, D]

// ===========================================================================
// Kernel 1: per-bond embedding hb  (grid B*E = 8192, block 256)
// ===========================================================================
__device__ __forceinline__ void stats256(float x, float* red, float& mu, float& rs) {
    float sx = x, sq = x * x;
#pragma unroll
    for (int o = 16; o; o >>= 1) {
        sx += __shfl_xor_sync(0xffffffffu, sx, o);
        sq += __shfl_xor_sync(0xffffffffu, sq, o);
    }
    int w = threadIdx.x >> 5;
    __syncthreads();
    if ((threadIdx.x & 31) == 0) { red[w] = sx; red[8 + w] = sq; }
    __syncthreads();
    float tx = 0.f, tq = 0.f;
#pragma unroll
    for (int k = 0; k < 8; k++) { tx += red[k]; tq += red[8 + k]; }
    mu = tx * (1.0f / 256.0f);
    rs = rsqrtf(fmaf(tq, 1.0f / 256.0f, -mu * mu) + 1e-5f);
}

__global__ void __launch_bounds__(256) hb_kernel(
    const int*   __restrict__ bfc,   // [B,E,3]
    const float* __restrict__ bff,   // [B,E,4]
    const float* __restrict__ mask,  // [B,E]
    const float* __restrict__ tbc,   // [33,256]
    const float* __restrict__ g1, const float* __restrict__ b1,
    const float* __restrict__ Wbf,   // [4,256]
    const float* __restrict__ bbf,
    const float* __restrict__ g2, const float* __restrict__ b2)
{
    __shared__ float red[16];
    const int be = blockIdx.x;
    const int d  = threadIdx.x;

    const int c0 = __ldg(bfc + be * 3 + 0) + 1;       // starts_bc = {0,11,22}, +1
    const int c1 = __ldg(bfc + be * 3 + 1) + 12;
    const int c2 = __ldg(bfc + be * 3 + 2) + 23;
    float xc = __ldg(tbc + c0 * 256 + d)
             + __ldg(tbc + c1 * 256 + d)
             + __ldg(tbc + c2 * 256 + d);
    float mu, rs;
    stats256(xc, red, mu, rs);
    float lnc = (xc - mu) * rs * __ldg(g1 + d) + __ldg(b1 + d);

    const float x0 = __ldg(bff + be * 4 + 0);
    const float x1 = __ldg(bff + be * 4 + 1);
    const float x2 = __ldg(bff + be * 4 + 2);
    const float x3 = __ldg(bff + be * 4 + 3);
    float xp = __ldg(bbf + d)
             + x0 * __ldg(Wbf + d)
             + x1 * __ldg(Wbf + 256 + d)
             + x2 * __ldg(Wbf + 512 + d)
             + x3 * __ldg(Wbf + 768 + d);
    float mu2, rs2;
    stats256(xp, red, mu2, rs2);
    float lnp = (xp - mu2) * rs2 * __ldg(g2 + d) + __ldg(b2 + d);

    g_hb[be * 256 + d] = (lnc + lnp) * __ldg(mask + be);
}

// ===========================================================================
// Kernel 2: g_rev = g_hb @ W_rev + b_rev   (8192x256 @ 256x256)
//   16 rows/block, 256 threads (one column each), row-pairs packed in f32x2.
// ===========================================================================
__global__ void __launch_bounds__(256) rev_kernel(
    const float* __restrict__ Wrev,   // [256,256]
    const float* __restrict__ brev)   // [256]
{
    constexpr int RROWS = 16, RPAD = 20;           // 20*4B = 80B, 16B aligned
    __shared__ __align__(16) float As[256 * RPAD]; // As[k][r] transposed

    const int row0 = blockIdx.x * RROWS;
    const int t = threadIdx.x;

    for (int idx = t; idx < 256 * RROWS; idx += 256) {
        int r = idx >> 8;          // 0..15
        int k = idx & 255;         // coalesced read from g_hb
        As[k * RPAD + r] = g_hb[(row0 + r) * 256 + k];
    }
    __syncthreads();

    U64 acc[8];
#pragma unroll
    for (int p = 0; p < 8; p++) acc[p] = 0ULL;     // (0.f, 0.f)

#pragma unroll 4
    for (int k = 0; k < 256; k++) {
        U64 wd = f2dup(__ldg(Wrev + k * 256 + t));
        const ulonglong2* ap = (const ulonglong2*)(As + k * RPAD);
#pragma unroll
        for (int q = 0; q < 4; q++) {
            ulonglong2 a = ap[q];                  // rows 4q..4q+3 (broadcast)
            acc[2 * q]     = f2fma(a.x, wd, acc[2 * q]);
            acc[2 * q + 1] = f2fma(a.y, wd, acc[2 * q + 1]);
        }
    }

    const float bv = __ldg(brev + t);
#pragma unroll
    for (int p = 0; p < 8; p++) {
        float lo, hi; f2un(acc[p], lo, hi);
        g_rev[(row0 + 2 * p)     * 256 + t] = lo + bv;
        g_rev[(row0 + 2 * p + 1) * 256 + t] = hi + bv;
    }
}

// ===========================================================================
// Kernel 3: fill out[b,i,j,:] for all (b,i,j).  Warp per pair, lane owns
//   d = {4L..4L+3} U {128+4L..128+4L+3}  (two float4 chunks, coalesced).
//   table_sc in SMEM; W_sf + LN params in registers (f32x2-packed).
// ===========================================================================
__device__ __forceinline__ void load4(const float* __restrict__ p, int lane, U64 v[4]) {
    float4 a = __ldg((const float4*)p + lane);
    float4 b = __ldg((const float4*)p + 32 + lane);
    v[0] = f2pk(a.x, a.y); v[1] = f2pk(a.z, a.w);
    v[2] = f2pk(b.x, b.y); v[3] = f2pk(b.z, b.w);
}

__device__ __forceinline__ void warpln(U64 a, U64 b, U64 c, U64 d, float& mu, float& rs) {
    U64 s = f2add(f2add(a, b), f2add(c, d));
    U64 q = f2fma(a, a, f2fma(b, b, f2fma(c, c, f2mul(d, d))));
    float sl, sh, ql, qh;
    f2un(s, sl, sh); f2un(q, ql, qh);
    float sx = sl + sh, sq = ql + qh;
#pragma unroll
    for (int o = 16; o; o >>= 1) {
        sx += __shfl_xor_sync(0xffffffffu, sx, o);
        sq += __shfl_xor_sync(0xffffffffu, sq, o);
    }
    mu = sx * (1.0f / 256.0f);
    rs = rsqrtf(fmaf(sq, 1.0f / 256.0f, -mu * mu) + 1e-5f);
}

__device__ __forceinline__ U64 lnapply(U64 x, U64 g, U64 bb, U64 nmu, U64 rs) {
    U64 rg = f2mul(g, rs);          // rstd * gamma
    U64 kk = f2fma(rg, nmu, bb);    // beta - mu*rstd*gamma
    return f2fma(x, rg, kk);
}

__global__ void __launch_bounds__(128) fill_kernel(
    const int4*   __restrict__ sfc,   // [B*48*48] int4  (4 cate feats)
    const float4* __restrict__ sff,   // [B*48*48*2] float4 (8 float feats)
    const float*  __restrict__ tsc,   // [44,256]
    const float*  __restrict__ gsc_p, const float* __restrict__ bsc_p,
    const float*  __restrict__ Wsf,   // [8,256]
    const float*  __restrict__ bias_p,
    const float*  __restrict__ gsf_p, const float* __restrict__ bsf_p,
    const float*  __restrict__ ve,    // [256]
    float* __restrict__ out)
{
    __shared__ __align__(16) float s_tab[44 * 256];  // 45056 B
    __shared__ __align__(16) float s_ve[256];

    const int tid = threadIdx.x;
    for (int idx = tid; idx < 44 * 256; idx += 128) s_tab[idx] = __ldg(tsc + idx);
    for (int idx = tid; idx < 256;      idx += 128) s_ve[idx]  = __ldg(ve + idx);
    __syncthreads();

    const int lane = tid & 31;
    const int warp = tid >> 5;

    // per-lane hoisted parameters (for its 8 d's)
    U64 gsc[4], bsc[4], gsf[4], bsf[4], bias[4], wsf[8][4];
    load4(gsc_p, lane, gsc);
    load4(bsc_p, lane, bsc);
    load4(gsf_p, lane, gsf);
    load4(bsf_p, lane, bsf);
    load4(bias_p, lane, bias);
#pragma unroll
    for (int f = 0; f < 8; f++) load4(Wsf + f * 256, lane, wsf[f]);

    const ulonglong2* tb = (const ulonglong2*)s_tab;   // 64 ull2 per table row
    const ulonglong2* vv = (const ulonglong2*)s_ve;
    const ulonglong2 v0 = vv[lane], v1 = vv[32 + lane];

    const int nwarp = gridDim.x * 4;
    const int P = 128 * 49 * 49;                       // all (b,i,j)
    for (int gp = blockIdx.x * 4 + warp; gp < P; gp += nwarp) {
        int b   = gp / 2401;
        int rem = gp - b * 2401;
        int i   = rem / 49;
        int j   = rem - i * 49;

        ulonglong2* dst = (ulonglong2*)(out + (size_t)gp * 256);
        if (i == 0 || j == 0) {                        // virtual edge row/col
            dst[lane]      = v0;
            dst[32 + lane] = v1;
            continue;
        }

        const int poff = (b * 48 + (i - 1)) * 48 + (j - 1);
        const int4   ci = __ldg(sfc + poff);
        const float4 x0 = __ldg(sff + poff * 2);
        const float4 x1 = __ldg(sff + poff * 2 + 1);

        // ---- cate: sum of 4 table rows (starts_sc = {0,11,22,33}, +1) ----
        U64 c0, c1, c2, c3;
        {
            int r = (ci.x + 1) * 64;
            ulonglong2 q = tb[r + lane];      c0 = q.x; c1 = q.y;
            q = tb[r + 32 + lane];            c2 = q.x; c3 = q.y;
        }
        {
            int r = (ci.y + 12) * 64;
            ulonglong2 q = tb[r + lane];      c0 = f2add(c0, q.x); c1 = f2add(c1, q.y);
            q = tb[r + 32 + lane];            c2 = f2add(c2, q.x); c3 = f2add(c3, q.y);
        }
        {
            int r = (ci.z + 23) * 64;
            ulonglong2 q = tb[r + lane];      c0 = f2add(c0, q.x); c1 = f2add(c1, q.y);
            q = tb[r + 32 + lane];            c2 = f2add(c2, q.x); c3 = f2add(c3, q.y);
        }
        {
            int r = (ci.w + 34) * 64;
            ulonglong2 q = tb[r + lane];      c0 = f2add(c0, q.x); c1 = f2add(c1, q.y);
            q = tb[r + 32 + lane];            c2 = f2add(c2, q.x); c3 = f2add(c3, q.y);
        }
        float mu_c, rs_c;
        warpln(c0, c1, c2, c3, mu_c, rs_c);

        // ---- float projection: bias + x(8) @ W_sf ----
        U64 p0 = bias[0], p1 = bias[1], p2 = bias[2], p3 = bias[3];
        const float xv[8] = { x0.x, x0.y, x0.z, x0.w, x1.x, x1.y, x1.z, x1.w };
#pragma unroll
        for (int f = 0; f < 8; f++) {
            U64 xd = f2dup(xv[f]);
            p0 = f2fma(wsf[f][0], xd, p0);
            p1 = f2fma(wsf[f][1], xd, p1);
            p2 = f2fma(wsf[f][2], xd, p2);
            p3 = f2fma(wsf[f][3], xd, p3);
        }
        float mu_p, rs_p;
        warpln(p0, p1, p2, p3, mu_p, rs_p);

        // ---- apply both LNs and combine ----
        const U64 nmc = f2dup(-mu_c), rc = f2dup(rs_c);
        const U64 nmp = f2dup(-mu_p), rp = f2dup(rs_p);
        U64 o0 = f2add(lnapply(c0, gsc[0], bsc[0], nmc, rc), lnapply(p0, gsf[0], bsf[0], nmp, rp));
        U64 o1 = f2add(lnapply(c1, gsc[1], bsc[1], nmc, rc), lnapply(p1, gsf[1], bsf[1], nmp, rp));
        U64 o2 = f2add(lnapply(c2, gsc[2], bsc[2], nmc, rc), lnapply(p2, gsf[2], bsf[2], nmp, rp));
        U64 o3 = f2add(lnapply(c3, gsc[3], bsc[3], nmc, rc), lnapply(p3, gsf[3], bsf[3], nmp, rp));

        ulonglong2 w01; w01.x = o0; w01.y = o1;
        ulonglong2 w23; w23.x = o2; w23.y = o3;
        dst[lane]      = w01;
        dst[32 + lane] = w23;
    }
}

// ===========================================================================
// Kernel 4: scatter-add bonds (atomic: duplicate (i,j) pairs accumulate)
// ===========================================================================
__global__ void __launch_bounds__(256) scatter_kernel(
    const int* __restrict__ bidx,    // [B,2,E]
    float* __restrict__ out)
{
    const int be = blockIdx.x;
    const int b = be >> 6, e = be & 63;
    const int d = threadIdx.x;
    const int i0 = __ldg(bidx + (b * 2)     * 64 + e) + 1;
    const int i1 = __ldg(bidx + (b * 2 + 1) * 64 + e) + 1;
    const float hv = g_hb [be * 256 + d];
    const float rv = g_rev[be * 256 + d];
    atomicAdd(out + ((size_t)(b * 49 + i0) * 49 + i1) * 256 + d, hv);
    atomicAdd(out + ((size_t)(b * 49 + i1) * 49 + i0) * 256 + d, rv);
}

// ===========================================================================
extern "C" void kernel_launch(void* const* d_in, const int* in_sizes, int n_in,
                              void* d_out, int out_size)
{
    (void)in_sizes; (void)n_in; (void)out_size;

    const int*    bond_index = (const int*)   d_in[0];
    const int*    bfc        = (const int*)   d_in[1];
    const float*  bff        = (const float*) d_in[2];
    const float*  bmask      = (const float*) d_in[3];
    const int4*   sfc        = (const int4*)  d_in[4];
    const float4* sff        = (const float4*)d_in[5];
    const float*  tbc        = (const float*) d_in[6];
    const float*  ln_bc_g    = (const float*) d_in[7];
    const float*  ln_bc_b    = (const float*) d_in[8];
    const float*  W_bf       = (const float*) d_in[9];
    const float*  b_bf       = (const float*) d_in[10];
    const float*  ln_bf_g    = (const float*) d_in[11];
    const float*  ln_bf_b    = (const float*) d_in[12];
    const float*  tsc        = (const float*) d_in[13];
    const float*  ln_sc_g    = (const float*) d_in[14];
    const float*  ln_sc_b    = (const float*) d_in[15];
    const float*  W_sf       = (const float*) d_in[16];
    const float*  b_sf       = (const float*) d_in[17];
    const float*  ln_sf_g    = (const float*) d_in[18];
    const float*  ln_sf_b    = (const float*) d_in[19];
    const float*  ve         = (const float*) d_in[20];
    const float*  W_rev      = (const float*) d_in[21];
    const float*  b_rev      = (const float*) d_in[22];
    float* out = (float*)d_out;

    hb_kernel<<<8192, 256>>>(bfc, bff, bmask, tbc, ln_bc_g, ln_bc_b,
                             W_bf, b_bf, ln_bf_g, ln_bf_b);
    rev_kernel<<<512, 256>>>(W_rev, b_rev);
    fill_kernel<<<304, 128>>>(sfc, sff, tsc, ln_sc_g, ln_sc_b,
                              W_sf, b_sf, ln_sf_g, ln_sf_b, ve, out);
    scatter_kernel<<<8192, 256>>>(bond_index, out);
}

// round 7
// speedup vs baseline: 1.6579x; 1.6579x over previous
#include <cuda_runtime.h>
#include <cstdint>

// ---------------------------------------------------------------------------
// StructureEmbeddingLayer  B=128, N=48, E=64, D=256, M=49
// ---------------------------------------------------------------------------

typedef unsigned long long U64;

// ---- packed f32x2 helpers (sm_100+) ----
__device__ __forceinline__ U64 f2pk(float lo, float hi) {
    U64 r;
    asm("mov.b64 %0, {%1, %2};" : "=l"(r)
        : "r"(__float_as_uint(lo)), "r"(__float_as_uint(hi)));
    return r;
}
__device__ __forceinline__ void f2un(U64 v, float& lo, float& hi) {
    unsigned a, b;
    asm("mov.b64 {%0, %1}, %2;" : "=r"(a), "=r"(b) : "l"(v));
    lo = __uint_as_float(a); hi = __uint_as_float(b);
}
__device__ __forceinline__ U64 f2dup(float x) { return f2pk(x, x); }
__device__ __forceinline__ U64 f2add(U64 a, U64 b) {
    U64 r; asm("add.rn.f32x2 %0, %1, %2;" : "=l"(r) : "l"(a), "l"(b)); return r;
}
__device__ __forceinline__ U64 f2mul(U64 a, U64 b) {
    U64 r; asm("mul.rn.f32x2 %0, %1, %2;" : "=l"(r) : "l"(a), "l"(b)); return r;
}
__device__ __forceinline__ U64 f2fma(U64 a, U64 b, U64 c) {
    U64 r; asm("fma.rn.f32x2 %0, %1, %2, %3;" : "=l"(r) : "l"(a), "l"(b), "l"(c)); return r;
}

// ---- scratch (no cudaMalloc allowed) ----
__device__ float g_hb   [8192 * 256];   // masked bond embedding  [B*E, D]
__device__ float g_rev  [8192 * 256];   // hb @ W_rev + b_rev     [B*E, D]
__device__ float g_tsc_c[44 * 256];     // row-centered table_sc
__device__ float g_wsf_c[8 * 256];      // row-centered W_sf
__device__ float g_bsf_c[256];          // centered b_sf

// ===========================================================================
// Kernel 0: center rows of table_sc / W_sf / b_sf (makes LN means exactly 0)
// ===========================================================================
__global__ void __launch_bounds__(256) center_kernel(
    const float* __restrict__ tsc, const float* __restrict__ Wsf,
    const float* __restrict__ bsf)
{
    __shared__ float red[8];
    const int blk = blockIdx.x, t = threadIdx.x;
    const float* src; float* dst;
    if (blk < 44)      { src = tsc + blk * 256;        dst = g_tsc_c + blk * 256; }
    else if (blk < 52) { src = Wsf + (blk - 44) * 256; dst = g_wsf_c + (blk - 44) * 256; }
    else               { src = bsf;                    dst = g_bsf_c; }
    float v = __ldg(src + t);
    float s = v;
#pragma unroll
    for (int o = 16; o; o >>= 1) s += __shfl_xor_sync(0xffffffffu, s, o);
    if ((t & 31) == 0) red[t >> 5] = s;
    __syncthreads();
    float tot = 0.f;
#pragma unroll
    for (int k = 0; k < 8; k++) tot += red[k];
    dst[t] = v - tot * (1.0f / 256.0f);
}

// ===========================================================================
// Kernel 1: per-bond embedding hb  (grid B*E = 8192, block 256)
// ===========================================================================
__device__ __forceinline__ void stats256(float x, float* red, float& mu, float& rs) {
    float sx = x, sq = x * x;
#pragma unroll
    for (int o = 16; o; o >>= 1) {
        sx += __shfl_xor_sync(0xffffffffu, sx, o);
        sq += __shfl_xor_sync(0xffffffffu, sq, o);
    }
    int w = threadIdx.x >> 5;
    __syncthreads();
    if ((threadIdx.x & 31) == 0) { red[w] = sx; red[8 + w] = sq; }
    __syncthreads();
    float tx = 0.f, tq = 0.f;
#pragma unroll
    for (int k = 0; k < 8; k++) { tx += red[k]; tq += red[8 + k]; }
    mu = tx * (1.0f / 256.0f);
    rs = rsqrtf(fmaf(tq, 1.0f / 256.0f, -mu * mu) + 1e-5f);
}

__global__ void __launch_bounds__(256) hb_kernel(
    const int*   __restrict__ bfc,   // [B,E,3]
    const float* __restrict__ bff,   // [B,E,4]
    const float* __restrict__ mask,  // [B,E]
    const float* __restrict__ tbc,   // [33,256]
    const float* __restrict__ g1, const float* __restrict__ b1,
    const float* __restrict__ Wbf,   // [4,256]
    const float* __restrict__ bbf,
    const float* __restrict__ g2, const float* __restrict__ b2)
{
    __shared__ float red[16];
    const int be = blockIdx.x;
    const int d  = threadIdx.x;

    const int c0 = __ldg(bfc + be * 3 + 0) + 1;       // starts_bc = {0,11,22}, +1
    const int c1 = __ldg(bfc + be * 3 + 1) + 12;
    const int c2 = __ldg(bfc + be * 3 + 2) + 23;
    float xc = __ldg(tbc + c0 * 256 + d)
             + __ldg(tbc + c1 * 256 + d)
             + __ldg(tbc + c2 * 256 + d);
    float mu, rs;
    stats256(xc, red, mu, rs);
    float lnc = (xc - mu) * rs * __ldg(g1 + d) + __ldg(b1 + d);

    const float x0 = __ldg(bff + be * 4 + 0);
    const float x1 = __ldg(bff + be * 4 + 1);
    const float x2 = __ldg(bff + be * 4 + 2);
    const float x3 = __ldg(bff + be * 4 + 3);
    float xp = __ldg(bbf + d)
             + x0 * __ldg(Wbf + d)
             + x1 * __ldg(Wbf + 256 + d)
             + x2 * __ldg(Wbf + 512 + d)
             + x3 * __ldg(Wbf + 768 + d);
    float mu2, rs2;
    stats256(xp, red, mu2, rs2);
    float lnp = (xp - mu2) * rs2 * __ldg(g2 + d) + __ldg(b2 + d);

    g_hb[be * 256 + d] = (lnc + lnp) * __ldg(mask + be);
}

// ===========================================================================
// Kernel 2: g_rev = g_hb @ W_rev + b_rev   (8192x256 @ 256x256)
// ===========================================================================
__global__ void __launch_bounds__(256) rev_kernel(
    const float* __restrict__ Wrev,   // [256,256]
    const float* __restrict__ brev)   // [256]
{
    constexpr int RROWS = 16, RPAD = 20;
    __shared__ __align__(16) float As[256 * RPAD];

    const int row0 = blockIdx.x * RROWS;
    const int t = threadIdx.x;

    for (int idx = t; idx < 256 * RROWS; idx += 256) {
        int r = idx >> 8;
        int k = idx & 255;
        As[k * RPAD + r] = g_hb[(row0 + r) * 256 + k];
    }
    __syncthreads();

    U64 acc[8];
#pragma unroll
    for (int p = 0; p < 8; p++) acc[p] = 0ULL;

#pragma unroll 4
    for (int k = 0; k < 256; k++) {
        U64 wd = f2dup(__ldg(Wrev + k * 256 + t));
        const ulonglong2* ap = (const ulonglong2*)(As + k * RPAD);
#pragma unroll
        for (int q = 0; q < 4; q++) {
            ulonglong2 a = ap[q];
            acc[2 * q]     = f2fma(a.x, wd, acc[2 * q]);
            acc[2 * q + 1] = f2fma(a.y, wd, acc[2 * q + 1]);
        }
    }

    const float bv = __ldg(brev + t);
#pragma unroll
    for (int p = 0; p < 8; p++) {
        float lo, hi; f2un(acc[p], lo, hi);
        g_rev[(row0 + 2 * p)     * 256 + t] = lo + bv;
        g_rev[(row0 + 2 * p + 1) * 256 + t] = hi + bv;
    }
}

// ===========================================================================
// Kernel 3: virtual-edge rows/cols (pure bandwidth)
// ===========================================================================
__global__ void __launch_bounds__(256) ve_kernel(
    const float4* __restrict__ vev,   // [64] float4 view of ve[256]
    float4* __restrict__ out)
{
    const int stride = gridDim.x * 256;
    const int total = 128 * 97 * 64;          // float4 units
    for (int t = blockIdx.x * 256 + threadIdx.x; t < total; t += stride) {
        int d4 = t & 63;
        int r = t >> 6;                        // 0 .. 128*97-1
        int b = r / 97;
        int pos = r - b * 97;                  // 0..48: (0,j)   49..96: (i,0)
        size_t cell = (size_t)b * 2401 + (pos < 49 ? pos : (size_t)(pos - 48) * 49);
        out[cell * 64 + d4] = __ldg(vev + d4);
    }
}

// ===========================================================================
// Kernel 4: interior fill. Warp per pair, contiguous per-warp chunks,
//   metadata prefetch (reg +1 pair, L2 +8 pairs), centered LN (mu == 0).
//   Lane owns d = {4L..4L+3} U {128+4L..128+4L+3}.
// ===========================================================================
__device__ __forceinline__ void load4(const float* __restrict__ p, int lane, U64 v[4]) {
    float4 a = __ldg((const float4*)p + lane);
    float4 b = __ldg((const float4*)p + 32 + lane);
    v[0] = f2pk(a.x, a.y); v[1] = f2pk(a.z, a.w);
    v[2] = f2pk(b.x, b.y); v[3] = f2pk(b.z, b.w);
}

__global__ void __launch_bounds__(128, 3) fill_kernel(
    const int4*   __restrict__ sfc,   // [B*48*48] int4
    const float4* __restrict__ sff,   // [B*48*48*2] float4
    const float*  __restrict__ gsc_p, const float* __restrict__ bsc_p,
    const float*  __restrict__ gsf_p, const float* __restrict__ bsf_ln,
    float* __restrict__ out)
{
    __shared__ __align__(16) float s_tab[44 * 256];

    const int tid = threadIdx.x;
    {   // stage centered table via float4
        const float4* src = (const float4*)g_tsc_c;
        float4* dst = (float4*)s_tab;
        for (int idx = tid; idx < 44 * 64; idx += 128) dst[idx] = src[idx];
    }
    __syncthreads();

    const int lane = tid & 31;
    const int warp = tid >> 5;

    U64 gsc[4], gsf[4], bsum[4], bc[4], wsf[8][4];
    load4(gsc_p, lane, gsc);
    load4(gsf_p, lane, gsf);
    {
        U64 t1[4], t2[4];
        load4(bsc_p, lane, t1);
        load4(bsf_ln, lane, t2);
#pragma unroll
        for (int p = 0; p < 4; p++) bsum[p] = f2add(t1[p], t2[p]);
    }
    load4(g_bsf_c, lane, bc);
#pragma unroll
    for (int f = 0; f < 8; f++) load4(g_wsf_c + f * 256, lane, wsf[f]);

    const ulonglong2* tb = (const ulonglong2*)s_tab;

    const int TOT = 128 * 48 * 48;
    const int NW = gridDim.x * 4;
    const int gw = blockIdx.x * 4 + warp;
    const int chunk = (TOT + NW - 1) / NW;
    int q = gw * chunk;
    int qend = q + chunk; if (qend > TOT) qend = TOT;
    if (q >= qend) return;

    // incremental (b,i,j) decode + dst pointer
    int b = q / 2304;
    int rem = q - b * 2304;
    int i = rem / 48;
    int j = rem - i * 48;
    float* dst = out + ((size_t)((b * 49 + i + 1) * 49 + (j + 1))) * 256;

    // prefetch pair q
    int4   ci = __ldg(sfc + q);
    float4 x0 = __ldg(sff + 2 * q);
    float4 x1 = __ldg(sff + 2 * q + 1);

    while (q < qend) {
        const int4   cci = ci;
        const float4 cx0 = x0, cx1 = x1;
        const int qn = q + 1;
        if (qn < qend) {
            ci = __ldg(sfc + qn);
            x0 = __ldg(sff + 2 * qn);
            x1 = __ldg(sff + 2 * qn + 1);
        }
        if (qn + 8 < TOT) {
            asm volatile("prefetch.global.L2 [%0];" :: "l"(sfc + qn + 8));
            asm volatile("prefetch.global.L2 [%0];" :: "l"(sff + 2 * (qn + 8)));
        }

        // ---- cate: sum of 4 centered table rows (starts_sc+1 = {1,12,23,34}) ----
        U64 c0, c1, c2, c3;
        {
            int r = (cci.x + 1) * 64;
            ulonglong2 t = tb[r + lane];       c0 = t.x; c1 = t.y;
            t = tb[r + 32 + lane];             c2 = t.x; c3 = t.y;
        }
        {
            int r = (cci.y + 12) * 64;
            ulonglong2 t = tb[r + lane];       c0 = f2add(c0, t.x); c1 = f2add(c1, t.y);
            t = tb[r + 32 + lane];             c2 = f2add(c2, t.x); c3 = f2add(c3, t.y);
        }
        {
            int r = (cci.z + 23) * 64;
            ulonglong2 t = tb[r + lane];       c0 = f2add(c0, t.x); c1 = f2add(c1, t.y);
            t = tb[r + 32 + lane];             c2 = f2add(c2, t.x); c3 = f2add(c3, t.y);
        }
        {
            int r = (cci.w + 34) * 64;
            ulonglong2 t = tb[r + lane];       c0 = f2add(c0, t.x); c1 = f2add(c1, t.y);
            t = tb[r + 32 + lane];             c2 = f2add(c2, t.x); c3 = f2add(c3, t.y);
        }

        // ---- float projection (centered): bc + x(8) @ Wc ----
        U64 p0 = bc[0], p1 = bc[1], p2 = bc[2], p3 = bc[3];
        const float xv[8] = { cx0.x, cx0.y, cx0.z, cx0.w, cx1.x, cx1.y, cx1.z, cx1.w };
#pragma unroll
        for (int f = 0; f < 8; f++) {
            U64 xd = f2dup(xv[f]);
            p0 = f2fma(wsf[f][0], xd, p0);
            p1 = f2fma(wsf[f][1], xd, p1);
            p2 = f2fma(wsf[f][2], xd, p2);
            p3 = f2fma(wsf[f][3], xd, p3);
        }

        // ---- variances (means are exactly 0) — one interleaved reduction ----
        U64 qc = f2fma(c0, c0, f2fma(c1, c1, f2fma(c2, c2, f2mul(c3, c3))));
        U64 qp = f2fma(p0, p0, f2fma(p1, p1, f2fma(p2, p2, f2mul(p3, p3))));
        float qcl, qch, qpl, qph;
        f2un(qc, qcl, qch); f2un(qp, qpl, qph);
        float sc = qcl + qch, sp = qpl + qph;
#pragma unroll
        for (int o = 16; o; o >>= 1) {
            sc += __shfl_xor_sync(0xffffffffu, sc, o);
            sp += __shfl_xor_sync(0xffffffffu, sp, o);
        }
        const float rs_c = rsqrtf(fmaf(sc, 1.0f / 256.0f, 1e-5f));
        const float rs_p = rsqrtf(fmaf(sp, 1.0f / 256.0f, 1e-5f));
        const U64 rc = f2dup(rs_c), rp = f2dup(rs_p);

        // ---- out = c*(g_sc*rs_c) + p*(g_sf*rs_p) + (b_sc + b_sf) ----
        U64 o0 = f2fma(c0, f2mul(gsc[0], rc), bsum[0]); o0 = f2fma(p0, f2mul(gsf[0], rp), o0);
        U64 o1 = f2fma(c1, f2mul(gsc[1], rc), bsum[1]); o1 = f2fma(p1, f2mul(gsf[1], rp), o1);
        U64 o2 = f2fma(c2, f2mul(gsc[2], rc), bsum[2]); o2 = f2fma(p2, f2mul(gsf[2], rp), o2);
        U64 o3 = f2fma(c3, f2mul(gsc[3], rc), bsum[3]); o3 = f2fma(p3, f2mul(gsf[3], rp), o3);

        ulonglong2* dv = (ulonglong2*)dst;
        ulonglong2 w01; w01.x = o0; w01.y = o1;
        ulonglong2 w23; w23.x = o2; w23.y = o3;
        dv[lane]      = w01;
        dv[32 + lane] = w23;

        // advance
        q = qn;
        dst += 256;
        if (++j == 48) {
            j = 0; dst += 256;                 // skip (i+1, 0)
            if (++i == 48) { i = 0; dst += 49 * 256; }   // skip row (b+1, 0, :)
        }
    }
}

// ===========================================================================
// Kernel 5: scatter-add bonds (atomic: duplicate (i,j) pairs accumulate)
// ===========================================================================
__global__ void __launch_bounds__(256) scatter_kernel(
    const int* __restrict__ bidx,    // [B,2,E]
    float* __restrict__ out)
{
    const int be = blockIdx.x;
    const int b = be >> 6, e = be & 63;
    const int d = threadIdx.x;
    const int i0 = __ldg(bidx + (b * 2)     * 64 + e) + 1;
    const int i1 = __ldg(bidx + (b * 2 + 1) * 64 + e) + 1;
    const float hv = g_hb [be * 256 + d];
    const float rv = g_rev[be * 256 + d];
    atomicAdd(out + ((size_t)(b * 49 + i0) * 49 + i1) * 256 + d, hv);
    atomicAdd(out + ((size_t)(b * 49 + i1) * 49 + i0) * 256 + d, rv);
}

// ===========================================================================
extern "C" void kernel_launch(void* const* d_in, const int* in_sizes, int n_in,
                              void* d_out, int out_size)
{
    (void)in_sizes; (void)n_in; (void)out_size;

    const int*    bond_index = (const int*)   d_in[0];
    const int*    bfc        = (const int*)   d_in[1];
    const float*  bff        = (const float*) d_in[2];
    const float*  bmask      = (const float*) d_in[3];
    const int4*   sfc        = (const int4*)  d_in[4];
    const float4* sff        = (const float4*)d_in[5];
    const float*  tbc        = (const float*) d_in[6];
    const float*  ln_bc_g    = (const float*) d_in[7];
    const float*  ln_bc_b    = (const float*) d_in[8];
    const float*  W_bf       = (const float*) d_in[9];
    const float*  b_bf       = (const float*) d_in[10];
    const float*  ln_bf_g    = (const float*) d_in[11];
    const float*  ln_bf_b    = (const float*) d_in[12];
    const float*  tsc        = (const float*) d_in[13];
    const float*  ln_sc_g    = (const float*) d_in[14];
    const float*  ln_sc_b    = (const float*) d_in[15];
    const float*  W_sf       = (const float*) d_in[16];
    const float*  b_sf       = (const float*) d_in[17];
    const float*  ln_sf_g    = (const float*) d_in[18];
    const float*  ln_sf_b    = (const float*) d_in[19];
    const float*  ve         = (const float*) d_in[20];
    const float*  W_rev      = (const float*) d_in[21];
    const float*  b_rev      = (const float*) d_in[22];
    float* out = (float*)d_out;

    center_kernel<<<53, 256>>>(tsc, W_sf, b_sf);
    hb_kernel<<<8192, 256>>>(bfc, bff, bmask, tbc, ln_bc_g, ln_bc_b,
                             W_bf, b_bf, ln_bf_g, ln_bf_b);
    rev_kernel<<<512, 256>>>(W_rev, b_rev);
    ve_kernel<<<592, 256>>>((const float4*)ve, (float4*)out);
    fill_kernel<<<444, 128>>>(sfc, sff, ln_sc_g, ln_sc_b,
                              ln_sf_g, ln_sf_b, out);
    scatter_kernel<<<8192, 256>>>(bond_index, out);
}